// round 9
// baseline (speedup 1.0000x reference)
#include <cuda_runtime.h>
#include <cuda_fp16.h>
#include <cstdint>

// Problem shape
#define KM 4096   // rows of x / out
#define KP 4096   // inner dim
#define KN 8192   // rows of weight / cols of out

// GEMM tiling: CTA 128x128, 4 warps, warp tile 64x64
#define BM 128
#define BN 128
#define BK 64
#define STAGES 3
#define KSTEPS (KP / BK)                 // 64
#define A_STAGE_BYTES (BM * BK * 2)      // 16384
#define B_STAGE_BYTES (BN * BK * 2)      // 16384
#define STAGE_BYTES (A_STAGE_BYTES + B_STAGE_BYTES)   // 32768
#define SMEM_TOTAL (STAGES * STAGE_BYTES)             // 98304

// fp16 scratch (row-major)
__device__ __half g_Xh[(size_t)KM * KP];   // 32 MB
__device__ __half g_Wh[(size_t)KN * KP];   // 64 MB

#define NX32 ((KM * KP) / 32)   // 524288 x-chunks (32 elems)
#define NW32 ((KN * KP) / 32)   // 1048576 w-chunks

// ---------------------------------------------------------------------------
__device__ __forceinline__ uint32_t s2u(const void* p) {
    uint32_t a;
    asm("{ .reg .u64 t; cvta.to.shared.u64 t, %1; cvt.u32.u64 %0, t; }"
        : "=r"(a) : "l"(p));
    return a;
}

__device__ __forceinline__ void cp_async16(uint32_t dst, const void* src) {
    asm volatile("cp.async.cg.shared.global [%0], [%1], 16;" :: "r"(dst), "l"(src));
}
__device__ __forceinline__ void cp_commit() {
    asm volatile("cp.async.commit_group;" ::: "memory");
}
template <int N>
__device__ __forceinline__ void cp_wait() {
    asm volatile("cp.async.wait_group %0;" :: "n"(N) : "memory");
}

__device__ __forceinline__ void ldsm_x4(uint32_t* r, uint32_t addr) {
    asm volatile("ldmatrix.sync.aligned.m8n8.x4.shared.b16 {%0,%1,%2,%3}, [%4];"
                 : "=r"(r[0]), "=r"(r[1]), "=r"(r[2]), "=r"(r[3]) : "r"(addr));
}

#define MMA16816(d, a, b0, b1)                                          \
    asm volatile(                                                       \
        "mma.sync.aligned.m16n8k16.row.col.f32.f16.f16.f32 "            \
        "{%0,%1,%2,%3}, {%4,%5,%6,%7}, {%8,%9}, {%0,%1,%2,%3};"         \
        : "+f"((d)[0]), "+f"((d)[1]), "+f"((d)[2]), "+f"((d)[3])        \
        : "r"((a)[0]), "r"((a)[1]), "r"((a)[2]), "r"((a)[3]),           \
          "r"(b0), "r"(b1))

// swizzled byte offset within a [rows x 64-half] tile (128B rows, 16B chunks)
__device__ __forceinline__ uint32_t swz(int row, int chunk) {
    return (uint32_t)row * 128u + (uint32_t)((chunk ^ (row & 7)) << 4);
}

// ---------------------------------------------------------------------------
// Pass 1: fp32 -> fp16 for BOTH x and weight, 32 elems / thread
// (128B read + 64B write per thread, 4 independent load/store pairs
//  for deeper MLP; convert pass measured at 6.7 TB/s, pushing toward spec)
// ---------------------------------------------------------------------------
__global__ void __launch_bounds__(256) convert_all_kernel(const float* __restrict__ x,
                                                          const float* __restrict__ w) {
    int i = blockIdx.x * 256 + threadIdx.x;
    const float* src;
    __half* dst;
    int j;
    if (i < NX32) {
        src = x;  dst = g_Xh;  j = i;
    } else {
        src = w;  dst = g_Wh;  j = i - NX32;
        if (j >= NW32) return;
    }
    const float4* s = reinterpret_cast<const float4*>(src) + (size_t)j * 8;
    uint4* d = reinterpret_cast<uint4*>(dst) + (size_t)j * 4;

    float4 f[8];
    #pragma unroll
    for (int q = 0; q < 8; q++) f[q] = __ldg(s + q);

    #pragma unroll
    for (int q = 0; q < 4; q++) {
        alignas(16) __half2 h[4];
        h[0] = __floats2half2_rn(f[q * 2].x,     f[q * 2].y);
        h[1] = __floats2half2_rn(f[q * 2].z,     f[q * 2].w);
        h[2] = __floats2half2_rn(f[q * 2 + 1].x, f[q * 2 + 1].y);
        h[3] = __floats2half2_rn(f[q * 2 + 1].z, f[q * 2 + 1].w);
        d[q] = *reinterpret_cast<const uint4*>(h);
    }
}

// ---------------------------------------------------------------------------
// Pass 2: mma.sync fp16 GEMM, 128x128 CTA tile, 4 warps (warp tile 64x64),
// 3-stage cp.async smem pipeline + register double-buffered fragments.
// (Exact R7 configuration — measured best: gemm 592.5us, tensor 76.5%.
//  Four scheduling interventions were neutral -> fp32-acc HMMA path is
//  saturated; this is the mma.sync practical ceiling on sm_103a.)
// ---------------------------------------------------------------------------
__global__ void __launch_bounds__(128, 2) gemm_kernel(const float* __restrict__ bias,
                                                      float* __restrict__ out) {
    extern __shared__ char smem[];
    const uint32_t sb = s2u(smem);
    const int tid = threadIdx.x;
    const int lane = tid & 31;
    const int wid = tid >> 5;   // 0..3
    const int nt = blockIdx.x;  // 0..63
    const int mt = blockIdx.y;  // 0..31

    const __half* gA0 = g_Xh + (size_t)(mt * BM) * KP;
    const __half* gW0 = g_Wh + (size_t)(nt * BN) * KP;

    // per-thread load slots: 8 A chunks + 8 B chunks of 16B each (128 threads)
    int lrow[8], lcol[8];
    #pragma unroll
    for (int i = 0; i < 8; i++) {
        int idx = i * 128 + tid;
        lrow[i] = idx >> 3;
        lcol[i] = idx & 7;
    }

    auto load_stage = [&](int ks, int buf) {
        uint32_t sA = sb + buf * STAGE_BYTES;
        uint32_t sB = sA + A_STAGE_BYTES;
        const __half* gA = gA0 + ks * BK;
        const __half* gB = gW0 + ks * BK;
        #pragma unroll
        for (int i = 0; i < 8; i++) {
            uint32_t off = swz(lrow[i], lcol[i]);
            cp_async16(sA + off, gA + (size_t)lrow[i] * KP + lcol[i] * 8);
            cp_async16(sB + off, gB + (size_t)lrow[i] * KP + lcol[i] * 8);
        }
    };

    // prologue: stages 0 .. STAGES-2
    #pragma unroll
    for (int s = 0; s < STAGES - 1; s++) {
        load_stage(s, s);
        cp_commit();
    }

    const int wm = (wid & 1) * 64;
    const int wn = (wid >> 1) * 64;

    float acc[4][8][4];
    #pragma unroll
    for (int mi = 0; mi < 4; mi++)
        #pragma unroll
        for (int ni = 0; ni < 8; ni++)
            #pragma unroll
            for (int q = 0; q < 4; q++) acc[mi][ni][q] = 0.0f;

    // ldmatrix lane addressing (constant over the loop)
    const int arow = lane & 15;
    const int achunk = lane >> 4;
    const int brow = (lane & 7) + ((lane >> 4) << 3);
    const int bchunk = (lane >> 3) & 1;

    uint32_t a[2][4][4], b[2][4][4];   // double-buffered fragments

    auto load_frags = [&](uint32_t sA, uint32_t sB, int kk, int slot) {
        #pragma unroll
        for (int mi = 0; mi < 4; mi++)
            ldsm_x4(a[slot][mi], sA + swz(wm + mi * 16 + arow, kk * 2 + achunk));
        #pragma unroll
        for (int nj = 0; nj < 4; nj++)
            ldsm_x4(b[slot][nj], sB + swz(wn + nj * 16 + brow, kk * 2 + bchunk));
    };

    for (int ks = 0; ks < KSTEPS; ks++) {
        cp_wait<STAGES - 2>();
        __syncthreads();

        if (ks + STAGES - 1 < KSTEPS)
            load_stage(ks + STAGES - 1, (ks + STAGES - 1) % STAGES);
        cp_commit();

        uint32_t sA = sb + (ks % STAGES) * STAGE_BYTES;
        uint32_t sB = sA + A_STAGE_BYTES;

        load_frags(sA, sB, 0, 0);

        #pragma unroll
        for (int kk = 0; kk < BK / 16; kk++) {
            const int cur = kk & 1;
            if (kk + 1 < BK / 16)
                load_frags(sA, sB, kk + 1, cur ^ 1);
            #pragma unroll
            for (int mi = 0; mi < 4; mi++)
                #pragma unroll
                for (int ni = 0; ni < 8; ni++)
                    MMA16816(acc[mi][ni], a[cur][mi],
                             b[cur][ni >> 1][(ni & 1) * 2],
                             b[cur][ni >> 1][(ni & 1) * 2 + 1]);
        }
    }

    // ---- epilogue: direct gmem stores with bias ----
    const int orow0 = mt * BM + wm + (lane >> 2);
    const int ocol0 = nt * BN + wn + (lane & 3) * 2;

    #pragma unroll
    for (int ni = 0; ni < 8; ni++) {
        int col = ocol0 + ni * 8;
        float2 bv = *reinterpret_cast<const float2*>(bias + col);
        #pragma unroll
        for (int mi = 0; mi < 4; mi++) {
            int r0 = orow0 + mi * 16;
            float2 o0, o1;
            o0.x = acc[mi][ni][0] + bv.x;
            o0.y = acc[mi][ni][1] + bv.y;
            o1.x = acc[mi][ni][2] + bv.x;
            o1.y = acc[mi][ni][3] + bv.y;
            *reinterpret_cast<float2*>(out + (size_t)r0 * KN + col) = o0;
            *reinterpret_cast<float2*>(out + (size_t)(r0 + 8) * KN + col) = o1;
        }
    }
}

// ---------------------------------------------------------------------------
extern "C" void kernel_launch(void* const* d_in, const int* in_sizes, int n_in,
                              void* d_out, int out_size) {
    const float* x    = (const float*)d_in[0];   // [4096, 4096]
    const float* w    = (const float*)d_in[1];   // [8192, 4096]
    const float* bias = (const float*)d_in[2];   // [8192]
    float* out = (float*)d_out;                  // [4096, 8192]

    cudaFuncSetAttribute(gemm_kernel, cudaFuncAttributeMaxDynamicSharedMemorySize, SMEM_TOTAL);

    convert_all_kernel<<<(NX32 + NW32) / 256, 256>>>(x, w);

    dim3 grid(KN / BN, KM / BM);   // (64, 32)
    gemm_kernel<<<grid, 128, SMEM_TOTAL>>>(bias, out);
}

// round 10
// speedup vs baseline: 1.0301x; 1.0301x over previous
#include <cuda_runtime.h>
#include <cuda_fp16.h>
#include <cstdint>

// Problem shape
#define KM 4096   // rows of x / out
#define KP 4096   // inner dim
#define KN 8192   // rows of weight / cols of out

// GEMM tiling: CTA 128x128, 4 warps, warp tile 64x64
#define BM 128
#define BN 128
#define BK 64
#define STAGES 3
#define KSTEPS (KP / BK)                 // 64
#define A_STAGE_BYTES (BM * BK * 2)      // 16384
#define B_STAGE_BYTES (BN * BK * 2)      // 16384
#define STAGE_BYTES (A_STAGE_BYTES + B_STAGE_BYTES)   // 32768
#define SMEM_TOTAL (STAGES * STAGE_BYTES)             // 98304

// fp16 scratch (row-major)
__device__ __half g_Xh[(size_t)KM * KP];   // 32 MB
__device__ __half g_Wh[(size_t)KN * KP];   // 64 MB

#define NX16 ((KM * KP) / 16)
#define NW16 ((KN * KP) / 16)

// ---------------------------------------------------------------------------
__device__ __forceinline__ uint32_t s2u(const void* p) {
    uint32_t a;
    asm("{ .reg .u64 t; cvta.to.shared.u64 t, %1; cvt.u32.u64 %0, t; }"
        : "=r"(a) : "l"(p));
    return a;
}

__device__ __forceinline__ void cp_async16(uint32_t dst, const void* src) {
    asm volatile("cp.async.cg.shared.global [%0], [%1], 16;" :: "r"(dst), "l"(src));
}
__device__ __forceinline__ void cp_commit() {
    asm volatile("cp.async.commit_group;" ::: "memory");
}
template <int N>
__device__ __forceinline__ void cp_wait() {
    asm volatile("cp.async.wait_group %0;" :: "n"(N) : "memory");
}

__device__ __forceinline__ void ldsm_x4(uint32_t* r, uint32_t addr) {
    asm volatile("ldmatrix.sync.aligned.m8n8.x4.shared.b16 {%0,%1,%2,%3}, [%4];"
                 : "=r"(r[0]), "=r"(r[1]), "=r"(r[2]), "=r"(r[3]) : "r"(addr));
}

// streaming store: evict-first in L2 so output doesn't displace fp16 scratch
__device__ __forceinline__ void stg_cs_v2(float* p, float x, float y) {
    asm volatile("st.global.cs.v2.f32 [%0], {%1, %2};" :: "l"(p), "f"(x), "f"(y) : "memory");
}

#define MMA16816(d, a, b0, b1)                                          \
    asm volatile(                                                       \
        "mma.sync.aligned.m16n8k16.row.col.f32.f16.f16.f32 "            \
        "{%0,%1,%2,%3}, {%4,%5,%6,%7}, {%8,%9}, {%0,%1,%2,%3};"         \
        : "+f"((d)[0]), "+f"((d)[1]), "+f"((d)[2]), "+f"((d)[3])        \
        : "r"((a)[0]), "r"((a)[1]), "r"((a)[2]), "r"((a)[3]),           \
          "r"(b0), "r"(b1))

// swizzled byte offset within a [rows x 64-half] tile (128B rows, 16B chunks)
__device__ __forceinline__ uint32_t swz(int row, int chunk) {
    return (uint32_t)row * 128u + (uint32_t)((chunk ^ (row & 7)) << 4);
}

// ---------------------------------------------------------------------------
// Pass 1: fp32 -> fp16 for BOTH x and weight, 16 elems / thread
// (R7 configuration: measured 288MB @ ~7.5TB/s — at the DRAM floor)
// ---------------------------------------------------------------------------
__global__ void __launch_bounds__(256) convert_all_kernel(const float* __restrict__ x,
                                                          const float* __restrict__ w) {
    int i = blockIdx.x * 256 + threadIdx.x;
    const float* src;
    __half* dst;
    int j;
    if (i < NX16) {
        src = x;  dst = g_Xh;  j = i;
    } else {
        src = w;  dst = g_Wh;  j = i - NX16;
        if (j >= NW16) return;
    }
    const float4* s = reinterpret_cast<const float4*>(src) + (size_t)j * 4;
    uint4* d = reinterpret_cast<uint4*>(dst) + (size_t)j * 2;
    #pragma unroll
    for (int half = 0; half < 2; half++) {
        float4 f0 = s[half * 2 + 0];
        float4 f1 = s[half * 2 + 1];
        alignas(16) __half2 h[4];
        h[0] = __floats2half2_rn(f0.x, f0.y);
        h[1] = __floats2half2_rn(f0.z, f0.w);
        h[2] = __floats2half2_rn(f1.x, f1.y);
        h[3] = __floats2half2_rn(f1.z, f1.w);
        d[half] = *reinterpret_cast<const uint4*>(h);
    }
}

// ---------------------------------------------------------------------------
// Pass 2: mma.sync fp16 GEMM, 128x128 CTA tile, 4 warps (warp tile 64x64),
// 3-stage cp.async smem pipeline + register double-buffered fragments.
// (R7 configuration — measured best and stable: gemm 592us, tensor ~77%.)
// Epilogue uses st.global.cs so the 128MB output stream doesn't evict the
// fp16 scratch (96MB, ~L2-resident) from L2 mid-kernel.
// ---------------------------------------------------------------------------
__global__ void __launch_bounds__(128, 2) gemm_kernel(const float* __restrict__ bias,
                                                      float* __restrict__ out) {
    extern __shared__ char smem[];
    const uint32_t sb = s2u(smem);
    const int tid = threadIdx.x;
    const int lane = tid & 31;
    const int wid = tid >> 5;   // 0..3
    const int nt = blockIdx.x;  // 0..63
    const int mt = blockIdx.y;  // 0..31

    const __half* gA0 = g_Xh + (size_t)(mt * BM) * KP;
    const __half* gW0 = g_Wh + (size_t)(nt * BN) * KP;

    // per-thread load slots: 8 A chunks + 8 B chunks of 16B each (128 threads)
    int lrow[8], lcol[8];
    #pragma unroll
    for (int i = 0; i < 8; i++) {
        int idx = i * 128 + tid;
        lrow[i] = idx >> 3;
        lcol[i] = idx & 7;
    }

    auto load_stage = [&](int ks, int buf) {
        uint32_t sA = sb + buf * STAGE_BYTES;
        uint32_t sB = sA + A_STAGE_BYTES;
        const __half* gA = gA0 + ks * BK;
        const __half* gB = gW0 + ks * BK;
        #pragma unroll
        for (int i = 0; i < 8; i++) {
            uint32_t off = swz(lrow[i], lcol[i]);
            cp_async16(sA + off, gA + (size_t)lrow[i] * KP + lcol[i] * 8);
            cp_async16(sB + off, gB + (size_t)lrow[i] * KP + lcol[i] * 8);
        }
    };

    // prologue: stages 0 .. STAGES-2
    #pragma unroll
    for (int s = 0; s < STAGES - 1; s++) {
        load_stage(s, s);
        cp_commit();
    }

    const int wm = (wid & 1) * 64;
    const int wn = (wid >> 1) * 64;

    float acc[4][8][4];
    #pragma unroll
    for (int mi = 0; mi < 4; mi++)
        #pragma unroll
        for (int ni = 0; ni < 8; ni++)
            #pragma unroll
            for (int q = 0; q < 4; q++) acc[mi][ni][q] = 0.0f;

    // ldmatrix lane addressing (constant over the loop)
    const int arow = lane & 15;
    const int achunk = lane >> 4;
    const int brow = (lane & 7) + ((lane >> 4) << 3);
    const int bchunk = (lane >> 3) & 1;

    uint32_t a[2][4][4], b[2][4][4];   // double-buffered fragments

    auto load_frags = [&](uint32_t sA, uint32_t sB, int kk, int slot) {
        #pragma unroll
        for (int mi = 0; mi < 4; mi++)
            ldsm_x4(a[slot][mi], sA + swz(wm + mi * 16 + arow, kk * 2 + achunk));
        #pragma unroll
        for (int nj = 0; nj < 4; nj++)
            ldsm_x4(b[slot][nj], sB + swz(wn + nj * 16 + brow, kk * 2 + bchunk));
    };

    for (int ks = 0; ks < KSTEPS; ks++) {
        cp_wait<STAGES - 2>();
        __syncthreads();

        if (ks + STAGES - 1 < KSTEPS)
            load_stage(ks + STAGES - 1, (ks + STAGES - 1) % STAGES);
        cp_commit();

        uint32_t sA = sb + (ks % STAGES) * STAGE_BYTES;
        uint32_t sB = sA + A_STAGE_BYTES;

        load_frags(sA, sB, 0, 0);

        #pragma unroll
        for (int kk = 0; kk < BK / 16; kk++) {
            const int cur = kk & 1;
            if (kk + 1 < BK / 16)
                load_frags(sA, sB, kk + 1, cur ^ 1);
            #pragma unroll
            for (int mi = 0; mi < 4; mi++)
                #pragma unroll
                for (int ni = 0; ni < 8; ni++)
                    MMA16816(acc[mi][ni], a[cur][mi],
                             b[cur][ni >> 1][(ni & 1) * 2],
                             b[cur][ni >> 1][(ni & 1) * 2 + 1]);
        }
    }

    // ---- epilogue: streaming gmem stores with bias ----
    const int orow0 = mt * BM + wm + (lane >> 2);
    const int ocol0 = nt * BN + wn + (lane & 3) * 2;

    #pragma unroll
    for (int ni = 0; ni < 8; ni++) {
        int col = ocol0 + ni * 8;
        float2 bv = *reinterpret_cast<const float2*>(bias + col);
        #pragma unroll
        for (int mi = 0; mi < 4; mi++) {
            int r0 = orow0 + mi * 16;
            stg_cs_v2(out + (size_t)r0 * KN + col,
                      acc[mi][ni][0] + bv.x, acc[mi][ni][1] + bv.y);
            stg_cs_v2(out + (size_t)(r0 + 8) * KN + col,
                      acc[mi][ni][2] + bv.x, acc[mi][ni][3] + bv.y);
        }
    }
}

// ---------------------------------------------------------------------------
extern "C" void kernel_launch(void* const* d_in, const int* in_sizes, int n_in,
                              void* d_out, int out_size) {
    const float* x    = (const float*)d_in[0];   // [4096, 4096]
    const float* w    = (const float*)d_in[1];   // [8192, 4096]
    const float* bias = (const float*)d_in[2];   // [8192]
    float* out = (float*)d_out;                  // [4096, 8192]

    cudaFuncSetAttribute(gemm_kernel, cudaFuncAttributeMaxDynamicSharedMemorySize, SMEM_TOTAL);

    convert_all_kernel<<<(NX16 + NW16) / 256, 256>>>(x, w);

    dim3 grid(KN / BN, KM / BM);   // (64, 32)
    gemm_kernel<<<grid, 128, SMEM_TOTAL>>>(bias, out);
}